// round 16
// baseline (speedup 1.0000x reference)
#include <cuda_runtime.h>
#include <math.h>

// Problem constants (all shapes fixed by the dataset)
#define HH   768
#define H4   (HH / 4)       // 192 float4 per row
#define TT   512
#define NCC  8
#define NLL  8921
#define NCTT 4096
#define NNN  4

#define RB      32
#define ENC_NRB (NCTT / RB)                 // 128 row-blocks of encoding
#define LW_NRB  ((NLL + RB - 1) / RB)       // 279 row-blocks of label_weights
#define NPROD   (ENC_NRB + LW_NRB)          // 407 producer blocks
#define NCONS   8                           // consumer blocks (8 slices x 24 float4-cols)
#define NBLK    (NPROD + NCONS)             // 415 total

// Deterministic per-block partials (no atomics on data, every needed slot written each call)
__device__ float4 g_Cpart[ENC_NRB][H4];  // encoding row-block column sums
__device__ float4 g_Gpart[LW_NRB][H4];   // label_weights row-block column sums (pre-boundary part)
__device__ float4 g_Gfix[NCC][H4];       // post-boundary remainder of the straddling block
__device__ int    g_ticket;              // producer arrival count (reset each call by consumer 0)

// j-range boundaries: jsplit_c = ceil((512c-1)*8921/4096), jmax_c = ceil(512c*8921/4096)-1
__device__ __forceinline__ int jsplit_f(int c) {
    return (int)(((512LL * c - 1) * 8921 + 4095) >> 12);
}

// Compile-time tables for RB=32 (verified): segment c owns Gpart rows [RB_LO[c], RB_HI[c]);
// no jsplit is 32-aligned -> Gfix[1..7] always written.
__constant__ int c_RB_LO[8] = {0, 35, 70, 105, 140, 175, 210, 244};
__constant__ int c_RB_HI[8] = {35, 70, 105, 140, 175, 210, 244, 279};
__constant__ int c_JS[8]    = {0, 1113, 2229, 3344, 4459, 5574, 6689, 7804};
__constant__ int c_JM[8]    = {0, 1115, 2230, 3345, 4460, 5575, 6690, 7805};

__device__ __forceinline__ float4 f4add(float4 a, float4 b) {
    a.x += b.x; a.y += b.y; a.z += b.z; a.w += b.w; return a;
}
__device__ __forceinline__ float4 f4fma(float4 a, float s, float4 acc) {
    acc.x += a.x * s; acc.y += a.y * s; acc.z += a.z * s; acc.w += a.w * s; return acc;
}

__global__ void __launch_bounds__(192)
fused_kernel(const float4* __restrict__ enc,
             const float4* __restrict__ lw,
             const int*    __restrict__ ids_raw,
             float4*       __restrict__ out) {
    const int t = threadIdx.x;

    if (blockIdx.x < NPROD) {
        // ================= producers: exact R11 streaming (RB=32, float4) =================
        if (blockIdx.x < ENC_NRB) {
            const int rb = blockIdx.x;
            const float4* p = enc + (size_t)rb * RB * H4 + t;
            float4 a = make_float4(0.f, 0.f, 0.f, 0.f);
            float4 b = make_float4(0.f, 0.f, 0.f, 0.f);
#pragma unroll
            for (int r = 0; r < RB; r += 2) {
                a = f4add(a, p[(size_t)r * H4]);
                b = f4add(b, p[(size_t)(r + 1) * H4]);
            }
            g_Cpart[rb][t] = f4add(a, b);
        } else {
            const int rb = blockIdx.x - ENC_NRB;
            const int r0 = rb * RB;
            const int r1 = min(r0 + RB, NLL);
            int seg = 0;
#pragma unroll
            for (int c = 1; c <= 7; c++)
                if (jsplit_f(c) <= r0) seg = c;
            const int nb   = (seg < 7) ? jsplit_f(seg + 1) : NLL;
            const int rmid = min(r1, nb);

            const float4* p = lw + (size_t)r0 * H4 + t;
            float4 a = make_float4(0.f, 0.f, 0.f, 0.f);
            for (int r = r0; r < rmid; r++) { a = f4add(a, *p); p += H4; }
            g_Gpart[rb][t] = a;
            if (nb < r1) {   // straddle: remainder rows go to segment seg+1
                a = make_float4(0.f, 0.f, 0.f, 0.f);
                for (int r = nb; r < r1; r++) { a = f4add(a, *p); p += H4; }
                g_Gfix[seg + 1][t] = a;
            }
        }
        // release: all stores done -> publish, bump ticket
        __syncthreads();
        if (t == 0) {
            __threadfence();
            atomicAdd(&g_ticket, 1);
        }
        return;
    }

    // ================= consumers: spin until all producers publish, then combine =========
    // Deadlock-free without co-residency: producers (blocks 0..406) retire, freeing SMs
    // for consumers (407..414). Spin terminates once all 407 producers have bumped.
    if (t == 0) {
        volatile int* tk = &g_ticket;
        while (*tk < NPROD) __nanosleep(64);
        __threadfence();                              // acquire producers' partials
    }
    __syncthreads();

    const int slice = t / 24;                   // 0..7 == segment / chunk id
    const int lane  = t - slice * 24;           // 0..23
    const int col   = (blockIdx.x - NPROD) * 24 + lane;   // float4 column 0..191

    // --- segment sum of label_weights partials: <=35 independent predicated float4 loads ---
    const int lo = c_RB_LO[slice];
    const int hi = c_RB_HI[slice];
    float4 g0 = make_float4(0.f, 0.f, 0.f, 0.f);
    float4 g1 = make_float4(0.f, 0.f, 0.f, 0.f);
    float4 g2 = make_float4(0.f, 0.f, 0.f, 0.f);
    float4 g3 = make_float4(0.f, 0.f, 0.f, 0.f);
#pragma unroll
    for (int i = 0; i < 36; i += 4) {
        if (lo + i + 0 < hi) g0 = f4add(g0, g_Gpart[lo + i + 0][col]);
        if (lo + i + 1 < hi) g1 = f4add(g1, g_Gpart[lo + i + 1][col]);
        if (lo + i + 2 < hi) g2 = f4add(g2, g_Gpart[lo + i + 2][col]);
        if (lo + i + 3 < hi) g3 = f4add(g3, g_Gpart[lo + i + 3][col]);
    }
    float4 segG = f4add(f4add(g0, g1), f4add(g2, g3));
    if (slice >= 1) segG = f4add(segG, g_Gfix[slice][col]);

    // --- chunk sum: slice s owns encoding chunk s = Cpart rows [16s, 16s+16) ---
    float4 s0 = make_float4(0.f, 0.f, 0.f, 0.f);
    float4 s1 = make_float4(0.f, 0.f, 0.f, 0.f);
#pragma unroll
    for (int k = 0; k < 16; k += 2) {
        s0 = f4add(s0, g_Cpart[slice * 16 + k][col]);
        s1 = f4add(s1, g_Cpart[slice * 16 + k + 1][col]);
    }
    const float4 chunkS = f4add(s0, s1);

    // --- boundary rows of lw: A = lw[jmax], E = sum lw[jsplit..jmax-1] (<=2 rows) ---
    float4 A = make_float4(0.f, 0.f, 0.f, 0.f);
    float4 E = make_float4(0.f, 0.f, 0.f, 0.f);
    if (slice >= 1) {
        const int js = c_JS[slice], jm = c_JM[slice];
        A = lw[(size_t)jm * H4 + col];
        E = lw[(size_t)js * H4 + col];
        if (js + 1 < jm) E = f4add(E, lw[(size_t)(js + 1) * H4 + col]);
    }

    // --- cross-slice exchange through smem ---
    __shared__ float4 sm[8][24][4];
    sm[slice][lane][0] = segG;
    sm[slice][lane][1] = chunkS;
    sm[slice][lane][2] = A;
    sm[slice][lane][3] = E;
    __syncthreads();

    if (slice == 0) {
        float4 G[8], S[8], Av[8], Ev[8];
#pragma unroll
        for (int c = 0; c < 8; c++) {
            G[c]  = sm[c][lane][0];
            S[c]  = sm[c][lane][1];
            Av[c] = sm[c][lane][2];
            Ev[c] = sm[c][lane][3];
        }
        float4 P[NCC + 1];
        P[0] = make_float4(0.f, 0.f, 0.f, 0.f);
#pragma unroll
        for (int c = 0; c < NCC; c++) P[c + 1] = f4add(P[c], S[c]);
        const float4 Ptot = P[NCC];

        // decode note_end_chunk_ids: int32 (JAX default) or genuine int64
        int ids[NNN];
        {
            const int a0 = ids_raw[0], a1 = ids_raw[1], a2 = ids_raw[2], a3 = ids_raw[3];
            const bool ok32 = (a0 >= 0) && (a0 <= a1) && (a1 <= a2) && (a2 <= a3) && (a3 < NCC);
            if (ok32) {
                ids[0] = a0; ids[1] = a1; ids[2] = a2; ids[3] = a3;
            } else {
                const long long* q = (const long long*)ids_raw;
                ids[0] = (int)q[0]; ids[1] = (int)q[1]; ids[2] = (int)q[2]; ids[3] = (int)q[3];
            }
        }

        // note-weight table: W[n][c] = softmax-over-notes weight for positions in chunk c
        float W[NNN][NCC];
#pragma unroll
        for (int c = 0; c < NCC; c++) {
            int cnt = 0;
#pragma unroll
            for (int m = 0; m < NNN; m++) cnt += (ids[m] < c) ? 1 : 0;
            const float inv = (cnt > 0) ? (1.f / (float)cnt) : 0.f;
#pragma unroll
            for (int n = 0; n < NNN; n++)
                W[n][c] = (cnt == 0) ? (1.f / NNN) : ((ids[n] < c) ? inv : 0.f);
        }

        // final: score[n] = sum_c W[n][c]*G[c]*Ptot + sum_c dW*(A*P[c] + E*Ptot); sigmoid
#pragma unroll
        for (int n = 0; n < NNN; n++) {
            float4 acc = make_float4(0.f, 0.f, 0.f, 0.f);
#pragma unroll
            for (int c = 0; c < NCC; c++) {
                const float4 GP = make_float4(G[c].x * Ptot.x, G[c].y * Ptot.y,
                                              G[c].z * Ptot.z, G[c].w * Ptot.w);
                acc = f4fma(GP, W[n][c], acc);
            }
#pragma unroll
            for (int c = 1; c <= 7; c++) {
                const float dW = W[n][c - 1] - W[n][c];
                const float4 T = make_float4(Av[c].x * P[c].x + Ev[c].x * Ptot.x,
                                             Av[c].y * P[c].y + Ev[c].y * Ptot.y,
                                             Av[c].z * P[c].z + Ev[c].z * Ptot.z,
                                             Av[c].w * P[c].w + Ev[c].w * Ptot.w);
                acc = f4fma(T, dW, acc);
            }
            float4 o;
            o.x = 1.f / (1.f + expf(-acc.x));
            o.y = 1.f / (1.f + expf(-acc.y));
            o.z = 1.f / (1.f + expf(-acc.z));
            o.w = 1.f / (1.f + expf(-acc.w));
            out[n * H4 + col] = o;
        }
    }

    // ticket reset for next graph replay: exactly one resetter (consumer block 0),
    // after its own spin has passed (=> all producers already arrived this call).
    __syncthreads();
    if (blockIdx.x == NPROD && t == 0) atomicExch(&g_ticket, 0);
}

extern "C" void kernel_launch(void* const* d_in, const int* in_sizes, int n_in,
                              void* d_out, int out_size) {
    const float* enc = (const float*)d_in[0];   // encoding (4096, 768) f32 (16B-aligned)
    const float* lw  = (const float*)d_in[2];   // label_weights buffer, viewed (8921, 768) f32
    const int*   ids = (const int*)d_in[3];     // note_end_chunk_ids (4,) int32 or int64
    (void)in_sizes; (void)n_in; (void)out_size; // label_queries (d_in[1]) provably unused

    fused_kernel<<<NBLK, H4>>>((const float4*)enc, (const float4*)lw, ids, (float4*)d_out);
}